// round 16
// baseline (speedup 1.0000x reference)
#include <cuda_runtime.h>
#include <cstdint>

#define B_ 8
#define T_ 4096
#define D_ 256
#define H_ 256
#define G_ 768              // 3H
#define M_ (B_ * T_)        // 32768
#define CANARY 0x7FC00001u  // NaN pattern; h is always finite
#define NTILES 6144         // xgemm: 2 dirs x 256 m-tiles x 12 n-tiles
#define NHTILES 2048        // heads: 256 m-tiles x 8 n-blocks

// Scratch (static device allocations only)
// xg layout (scan-permuted): [d][b][t][rank(4)][w(8)][gate(3)][j(8)]
__device__ float g_xg[(size_t)2 * B_ * T_ * G_];
__device__ float g_outc[(size_t)B_ * T_ * 2 * H_];     // [b][t][512]  (fwd | bwd)
__device__ unsigned g_cnt[2 * 8 * 32];                 // [d][b][tc] xg tile counters
__device__ unsigned g_prog[2 * 8];                     // [d][b] scan progress (32/epoch)
__device__ unsigned g_tilectr;                         // xgemm work queue
__device__ unsigned g_headctr;                         // heads work queue

typedef unsigned long long ull;

__device__ __forceinline__ uint32_t s2u(const void* p) {
    uint32_t a;
    asm("{ .reg .u64 t; cvta.to.shared.u64 t, %1; cvt.u32.u64 %0, t; }"
        : "=r"(a) : "l"(p));
    return a;
}
__device__ __forceinline__ ull ffma2(ull a, ull b, ull c) {
    ull d;
    asm("fma.rn.f32x2 %0, %1, %2, %3;" : "=l"(d) : "l"(a), "l"(b), "l"(c));
    return d;
}
__device__ __forceinline__ ull fadd2(ull a, ull b) {
    ull d;
    asm("add.rn.f32x2 %0, %1, %2;" : "=l"(d) : "l"(a), "l"(b));
    return d;
}
__device__ __forceinline__ ull pack2(float lo, float hi) {
    ull r;
    asm("mov.b64 %0, {%1, %2};" : "=l"(r)
        : "r"(__float_as_uint(lo)), "r"(__float_as_uint(hi)));
    return r;
}
__device__ __forceinline__ ull dup2(float v) {
    ull r;
    asm("mov.b64 %0, {%1, %1};" : "=l"(r) : "r"(__float_as_uint(v)));
    return r;
}
__device__ __forceinline__ void unpack2(ull a, float& lo, float& hi) {
    uint32_t l, h;
    asm("mov.b64 {%0, %1}, %2;" : "=r"(l), "=r"(h) : "l"(a));
    lo = __uint_as_float(l); hi = __uint_as_float(h);
}
__device__ __forceinline__ float sum2(ull a) {
    float lo, hi; unpack2(a, lo, hi); return lo + hi;
}
__device__ __forceinline__ float fast_sigmoid(float x) {
    float e, r;
    asm("ex2.approx.f32 %0, %1;" : "=f"(e) : "f"(-1.4426950408889634f * x));
    asm("rcp.approx.f32 %0, %1;" : "=f"(r) : "f"(1.0f + e));
    return r;
}
__device__ __forceinline__ float fast_tanh(float x) {
    float e, r;
    asm("ex2.approx.f32 %0, %1;" : "=f"(e) : "f"(-2.8853900817779268f * x));
    asm("rcp.approx.f32 %0, %1;" : "=f"(r) : "f"(1.0f + e));
    return fmaf(2.0f, r, -1.0f);
}
__device__ __forceinline__ float fast_exp(float x) {
    float e;
    asm("ex2.approx.f32 %0, %1;" : "=f"(e) : "f"(1.4426950408889634f * x));
    return e;
}
__device__ __forceinline__ unsigned ldacq_g(const unsigned* p) {
    unsigned v;
    asm volatile("ld.acquire.gpu.global.u32 %0, [%1];" : "=r"(v) : "l"(p));
    return v;
}
__device__ __forceinline__ void wait_cnt12(const unsigned* p) {
    while (ldacq_g(p) < 12u) { }
}
__device__ __forceinline__ unsigned ldvol32(uint32_t a) {
    unsigned v;
    asm volatile("ld.volatile.shared.u32 %0, [%1];" : "=r"(v) : "r"(a) : "memory");
    return v;
}

// ---------------------------------------------------------------------------
// k_init: reset all counters (stream-ordered before k_mega).
// ---------------------------------------------------------------------------
__global__ void k_init() {
    int t = threadIdx.x;
    if (t < 512) g_cnt[t] = 0u;
    if (t < 16)  g_prog[t] = 0u;
    if (t == 0)  { g_tilectr = 0u; g_headctr = 0u; }
}

// ---------------------------------------------------------------------------
// One 128x64 xgemm tile (FFMA2, double-buffered), permuted store to g_xg.
// ---------------------------------------------------------------------------
__device__ __forceinline__ void gemm_tile(
    const float* __restrict__ X, const float* __restrict__ W,
    const float* __restrict__ bi, float* __restrict__ out,
    int m0, int n0,
    float (&As)[2][16][136], float (&Bs)[2][16][68])
{
    const int tid = threadIdx.x;
    const int ti = tid >> 4;
    const int tj = tid & 15;
    const int ar = tid >> 4, ac = tid & 15;
    const int br = tid >> 6, bc = tid & 63;

    ull acc2[4][4];
#pragma unroll
    for (int i = 0; i < 4; ++i)
#pragma unroll
        for (int j = 0; j < 4; ++j) acc2[i][j] = 0ull;

#pragma unroll
    for (int p = 0; p < 8; ++p)
        As[0][ac][ar + p * 16] = X[(size_t)(m0 + ar + p * 16) * D_ + ac];
#pragma unroll
    for (int p = 0; p < 4; ++p)
        Bs[0][br + p * 4][bc] = W[(size_t)(br + p * 4) * G_ + n0 + bc];
    __syncthreads();

    int buf = 0;
    for (int k0 = 0; k0 < D_; k0 += 16) {
        float xa[8], xb[4];
        if (k0 + 16 < D_) {
#pragma unroll
            for (int p = 0; p < 8; ++p)
                xa[p] = X[(size_t)(m0 + ar + p * 16) * D_ + k0 + 16 + ac];
#pragma unroll
            for (int p = 0; p < 4; ++p)
                xb[p] = W[(size_t)(k0 + 16 + br + p * 4) * G_ + n0 + bc];
        }
#pragma unroll
        for (int kk = 0; kk < 16; ++kk) {
            ull ap[4];
            const ull* arow = (const ull*)&As[buf][kk][ti * 8];
            ap[0] = arow[0]; ap[1] = arow[1]; ap[2] = arow[2]; ap[3] = arow[3];
            float4 bq = *(const float4*)&Bs[buf][kk][tj * 4];
            ull bd[4];
            bd[0] = dup2(bq.x); bd[1] = dup2(bq.y);
            bd[2] = dup2(bq.z); bd[3] = dup2(bq.w);
#pragma unroll
            for (int i = 0; i < 4; ++i)
#pragma unroll
                for (int j = 0; j < 4; ++j)
                    acc2[i][j] = ffma2(ap[i], bd[j], acc2[i][j]);
        }
        if (k0 + 16 < D_) {
#pragma unroll
            for (int p = 0; p < 8; ++p) As[buf ^ 1][ac][ar + p * 16] = xa[p];
#pragma unroll
            for (int p = 0; p < 4; ++p) Bs[buf ^ 1][br + p * 4][bc] = xb[p];
            __syncthreads();
            buf ^= 1;
        }
    }

    const int n = n0 + tj * 4;
    const int g = n >> 8, u = n & 255;
    const int pos = (u >> 6) * 192 + ((u >> 3) & 7) * 24 + g * 8 + (u & 7);
    float4 bb = *(const float4*)&bi[n];
#pragma unroll
    for (int i = 0; i < 4; ++i) {
        float4 o0, o1;
        unpack2(acc2[i][0], o0.x, o1.x);
        unpack2(acc2[i][1], o0.y, o1.y);
        unpack2(acc2[i][2], o0.z, o1.z);
        unpack2(acc2[i][3], o0.w, o1.w);
        o0.x += bb.x; o0.y += bb.y; o0.z += bb.z; o0.w += bb.w;
        o1.x += bb.x; o1.y += bb.y; o1.z += bb.z; o1.w += bb.w;
        *(float4*)&out[(size_t)(m0 + ti * 8 + i * 2)     * G_ + pos] = o0;
        *(float4*)&out[(size_t)(m0 + ti * 8 + i * 2 + 1) * G_ + pos] = o1;
    }
}

// ---------------------------------------------------------------------------
// One 128x64 heads tile (FFMA2, double-buffered, fast-exp epilogue).
// ---------------------------------------------------------------------------
__device__ __forceinline__ void heads_tile(
    const float* __restrict__ W, const float* __restrict__ bbp, bool isV,
    int m0, int nw, float* __restrict__ out,
    float (&As)[2][16][136], float (&Bs)[2][16][68])
{
    const int tid = threadIdx.x;
    const int ti = tid >> 4, tj = tid & 15;
    const int ar = tid >> 4, ac = tid & 15;
    const int br = tid >> 6, bc = tid & 63;

    ull acc2[4][4];
#pragma unroll
    for (int i = 0; i < 4; ++i)
#pragma unroll
        for (int j = 0; j < 4; ++j) acc2[i][j] = 0ull;

#pragma unroll
    for (int p = 0; p < 8; ++p)
        As[0][ac][ar + p * 16] = g_outc[(size_t)(m0 + ar + p * 16) * 512 + ac];
#pragma unroll
    for (int p = 0; p < 4; ++p)
        Bs[0][br + p * 4][bc] = W[(size_t)(br + p * 4) * 256 + nw + bc];
    __syncthreads();

    int buf = 0;
    for (int k0 = 0; k0 < 512; k0 += 16) {
        float xa[8], xb[4];
        if (k0 + 16 < 512) {
#pragma unroll
            for (int p = 0; p < 8; ++p)
                xa[p] = g_outc[(size_t)(m0 + ar + p * 16) * 512 + k0 + 16 + ac];
#pragma unroll
            for (int p = 0; p < 4; ++p)
                xb[p] = W[(size_t)(k0 + 16 + br + p * 4) * 256 + nw + bc];
        }
#pragma unroll
        for (int kk = 0; kk < 16; ++kk) {
            ull ap[4];
            const ull* arow = (const ull*)&As[buf][kk][ti * 8];
            ap[0] = arow[0]; ap[1] = arow[1]; ap[2] = arow[2]; ap[3] = arow[3];
            float4 bq = *(const float4*)&Bs[buf][kk][tj * 4];
            ull bd[4];
            bd[0] = dup2(bq.x); bd[1] = dup2(bq.y);
            bd[2] = dup2(bq.z); bd[3] = dup2(bq.w);
#pragma unroll
            for (int i = 0; i < 4; ++i)
#pragma unroll
                for (int jj = 0; jj < 4; ++jj)
                    acc2[i][jj] = ffma2(ap[i], bd[jj], acc2[i][jj]);
        }
        if (k0 + 16 < 512) {
#pragma unroll
            for (int p = 0; p < 8; ++p) As[buf ^ 1][ac][ar + p * 16] = xa[p];
#pragma unroll
            for (int p = 0; p < 4; ++p) Bs[buf ^ 1][br + p * 4][bc] = xb[p];
            __syncthreads();
            buf ^= 1;
        }
    }

    const size_t hofs = (size_t)M_ * H_;
    float4 bb4 = *(const float4*)&bbp[nw + tj * 4];
#pragma unroll
    for (int i = 0; i < 4; ++i) {
        float4 o0, o1;
        unpack2(acc2[i][0], o0.x, o1.x);
        unpack2(acc2[i][1], o0.y, o1.y);
        unpack2(acc2[i][2], o0.z, o1.z);
        unpack2(acc2[i][3], o0.w, o1.w);
        o0.x += bb4.x; o0.y += bb4.y; o0.z += bb4.z; o0.w += bb4.w;
        o1.x += bb4.x; o1.y += bb4.y; o1.z += bb4.z; o1.w += bb4.w;
        int r0 = m0 + ti * 8 + i * 2, r1 = r0 + 1;
        if (isV) {
            o0.x = fast_exp(o0.x); o0.y = fast_exp(o0.y);
            o0.z = fast_exp(o0.z); o0.w = fast_exp(o0.w);
            o1.x = fast_exp(o1.x); o1.y = fast_exp(o1.y);
            o1.z = fast_exp(o1.z); o1.w = fast_exp(o1.w);
            *(float4*)&out[(size_t)r0 * 256 + nw + tj * 4] = o0;
            *(float4*)&out[(size_t)r1 * 256 + nw + tj * 4] = o1;
        } else {
            *(float4*)&out[hofs + (size_t)r0 * 256 + nw + tj * 4] = o0;
            *(float4*)&out[hofs + (size_t)r1 * 256 + nw + tj * 4] = o1;
        }
    }
}

// ---------------------------------------------------------------------------
// heads_loop: pull heads tiles (unlock-epoch priority), wait on scan progress.
// ---------------------------------------------------------------------------
__device__ void heads_loop(
    const float* Wm, const float* bm, const float* Wv, const float* bv,
    float* out, float (&As)[2][16][136], float (&Bs)[2][16][68], int* s_idx)
{
    const int tid = threadIdx.x;
    for (;;) {
        if (tid == 0) *s_idx = (int)atomicAdd(&g_headctr, 1u);
        __syncthreads();
        const int hidx = *s_idx;
        if (hidx >= NHTILES) break;

        const int k   = hidx >> 7;
        const int sub = hidx & 127;
        const int tc  = (sub & 1) ? (16 + k) : (15 - k);
        const int b   = (sub >> 1) & 7;
        const int nb  = sub >> 4;
        const int m0  = (b * 32 + tc) * 128;
        const int n0  = nb * 64;
        const bool isV = (n0 >= 256);
        const int nw  = n0 & 255;

        const unsigned ef = (unsigned)(tc + 2);
        const unsigned eb = (unsigned)((tc == 0) ? 33 : (33 - tc));
        if (tid == 0) {
            const unsigned* pf = &g_prog[b];
            const unsigned* pb = &g_prog[8 + b];
            while (ldacq_g(pf) < 32u * ef) __nanosleep(256);
            while (ldacq_g(pb) < 32u * eb) __nanosleep(256);
        }
        __syncthreads();

        heads_tile(isV ? Wv : Wm, isV ? bv : bm, isV, m0, nw, out, As, Bs);
    }
}

// ---------------------------------------------------------------------------
// k_mega: 37 clusters x 4 CTAs.
//   blockIdx 0..63  : GRU scan (2-PHASE dots: own block overlaps the fabric)
//   blockIdx 64..147: xgemm workers -> heads workers.
// ---------------------------------------------------------------------------
__global__ void __launch_bounds__(256, 1) __cluster_dims__(4, 1, 1)
k_mega(const float* __restrict__ X,
       const float* __restrict__ Wi_f, const float* __restrict__ bi_f,
       const float* __restrict__ Wi_b, const float* __restrict__ bi_b,
       const float* __restrict__ Wh_f, const float* __restrict__ bhn_f,
       const float* __restrict__ Wh_b, const float* __restrict__ bhn_b,
       const float* __restrict__ Wm, const float* __restrict__ bm,
       const float* __restrict__ Wv, const float* __restrict__ bv,
       float* __restrict__ out)
{
    __shared__ __align__(16) float As[2][16][136];
    __shared__ __align__(16) float Bs[2][16][68];
    __shared__ __align__(16) float hbuf[4][272];
    __shared__ __align__(16) float hist[16][64];
    __shared__ int s_idx;

    const int tid = threadIdx.x;

    if (blockIdx.x >= 64) {
        // ================= WORKER PATH =================
        for (;;) {
            if (tid == 0) s_idx = (int)atomicAdd(&g_tilectr, 1u);
            __syncthreads();
            const int idx = s_idx;
            if (idx >= NTILES) break;

            const int k  = idx / 96;
            const int r  = idx - k * 96;
            const int bb = r / 12;
            const int bx = r - bb * 12;
            const int dd = k & 1;
            const int ii = k >> 1;
            const int tc = dd ? (31 - ii) : ii;
            const int m0 = (bb * 32 + tc) * 128;
            const int n0 = bx * 64;

            gemm_tile(X, dd ? Wi_b : Wi_f, dd ? bi_b : bi_f,
                      g_xg + (size_t)dd * M_ * G_, m0, n0, As, Bs);

            __threadfence();
            __syncthreads();
            if (tid == 0) {
                const unsigned* p = &g_cnt[(dd * 8 + bb) * 32 + tc];
                asm volatile("red.release.gpu.global.add.u32 [%0], %1;"
                             :: "l"(p), "r"(1u) : "memory");
            }
        }
        heads_loop(Wm, bm, Wv, bv, out, As, Bs, &s_idx);
        return;
    }

    // ================= SCAN PATH =================
    const uint32_t hbuf_a = s2u(hbuf);

    const int rank = blockIdx.x & 3;
    const int cid  = blockIdx.x >> 2;
    const int d    = cid >> 3;
    const int b    = cid & 7;

    const float* Wh  = d ? Wh_b  : Wh_f;
    const float* bhn = d ? bhn_b : bhn_f;

    const int w    = tid >> 5;
    const int lane = tid & 31;
    const int ss   = lane >> 3;                    // K sub-slot (0..3)
    const int j    = lane & 7;                     // unit within warp (0..7)
    const int unit = rank * 64 + w * 8 + j;
    const unsigned* cbase = &g_cnt[(d * 8 + b) * 32];
    unsigned* prog = &g_prog[d * 8 + b];

    // W registers, PHASE-interleaved: phase i covers block (rank+i)&3,
    // lane's 16 K-values at blk*64 + ss*16 .. +16. Phase 0 = OWN block.
    ull Wr2[32], Wz2[32], Wn2[32];
#pragma unroll
    for (int i = 0; i < 4; ++i) {
        const int blk = (rank + i) & 3;
#pragma unroll
        for (int m = 0; m < 8; ++m) {
            const int kg = blk * 64 + ss * 16 + m * 2;
            size_t r0 = (size_t)kg * G_;
            size_t r1 = r0 + G_;
            Wr2[i * 8 + m] = pack2(__ldg(Wh + r0 + unit),       __ldg(Wh + r1 + unit));
            Wz2[i * 8 + m] = pack2(__ldg(Wh + r0 + 256 + unit), __ldg(Wh + r1 + 256 + unit));
            Wn2[i * 8 + m] = pack2(__ldg(Wh + r0 + 512 + unit), __ldg(Wh + r1 + 512 + unit));
        }
    }

    for (int i = tid; i < 272; i += 256) {
        hbuf[0][i] = 0.f;
        ((unsigned*)hbuf[1])[i] = CANARY;
        ((unsigned*)hbuf[2])[i] = CANARY;
        ((unsigned*)hbuf[3])[i] = CANARY;
    }
    __syncthreads();
    asm volatile("barrier.cluster.arrive.aligned;" ::: "memory");
    asm volatile("barrier.cluster.wait.aligned;"   ::: "memory");

    // coalesced sends (unchanged from R10): lanes 0..7, peer (rank+(lane>>1))&3
    uint32_t sdata = 0;
    if (lane < 8) {
        uint32_t peer = (uint32_t)((rank + (lane >> 1)) & 3);
        uint32_t rhb;
        asm("mapa.shared::cluster.u32 %0, %1, %2;" : "=r"(rhb) : "r"(hbuf_a), "r"(peer));
        sdata = rhb + (uint32_t)(rank * 272 + w * 32 + (lane & 1) * 16);
    }

    // poll addresses: own block (phase A) and 3 remote blocks (phase B);
    // lane covers word `lane` and `lane+32` of each 64-word block.
    const uint32_t pA  = hbuf_a + (uint32_t)(rank * 68 + lane) * 4;
    const uint32_t pB1 = hbuf_a + (uint32_t)(((rank + 1) & 3) * 68 + lane) * 4;
    const uint32_t pB2 = hbuf_a + (uint32_t)(((rank + 2) & 3) * 68 + lane) * 4;
    const uint32_t pB3 = hbuf_a + (uint32_t)(((rank + 3) & 3) * 68 + lane) * 4;

    // data bases per phase (float offsets within hbuf[q])
    const int dbA  = rank * 68 + ss * 16;
    const int dbB1 = ((rank + 1) & 3) * 68 + ss * 16;
    const int dbB2 = ((rank + 2) & 3) * 68 + ss * 16;
    const int dbB3 = ((rank + 3) & 3) * 68 + ss * 16;

    // re-canary partition (unchanged): warp w owns block (w>>1), half (w&1)
    const uint32_t ca = hbuf_a + (uint32_t)((w >> 1) * 272 + (w & 1) * 128 + lane * 4);

    const float bhn_u = bhn[unit];
    const float* xgp = g_xg + ((size_t)(d * B_ + b)) * T_ * G_ + rank * 192 + w * 24;

    wait_cnt12(cbase + (d ? 31 : 0));
    wait_cnt12(cbase + (d ? 30 : 1));

    float gv0 = 0.f, gv1 = 0.f, gv2 = 0.f;
    if (lane < 24) {
        gv0 = __ldg(xgp + (size_t)(d ? T_ - 1 : 0) * G_ + lane);
        gv1 = __ldg(xgp + (size_t)(d ? T_ - 2 : 1) * G_ + lane);
        gv2 = __ldg(xgp + (size_t)(d ? T_ - 3 : 2) * G_ + lane);
    }

    float hprev = 0.f;

    for (int s = 0; s < T_; ++s) {
        const int q = s & 3;
        const uint32_t qb = (uint32_t)q * 1088;
        const float* hq = hbuf[q];

        if ((s & 127) == 0 && s) {
            const int a = s >> 7;
            const int c0 = d ? (31 - a) : a;
            const int c1n = (a < 31) ? (a + 1) : 31;
            const int c1 = d ? (31 - c1n) : c1n;
            wait_cnt12(cbase + c0);
            wait_cnt12(cbase + c1);
        }

        ull ar0 = 0, ar1 = 0, az0 = 0, az1 = 0, an0 = 0, an1 = 0;

        // ---- PHASE A: poll OWN block (local self-send, ~40cyc) + dots ----
        while (__any_sync(0xFFFFFFFFu,
                (ldvol32(pA + qb) == CANARY) | (ldvol32(pA + qb + 128) == CANARY))) { }
        {
            const float* hp = hq + dbA;
            ulonglong2 h0 = *(const ulonglong2*)(hp);
            ulonglong2 h1 = *(const ulonglong2*)(hp + 4);
            ulonglong2 h2 = *(const ulonglong2*)(hp + 8);
            ulonglong2 h3 = *(const ulonglong2*)(hp + 12);
            ar0 = ffma2(Wr2[0], h0.x, ar0); ar1 = ffma2(Wr2[1], h0.y, ar1);
            az0 = ffma2(Wz2[0], h0.x, az0); az1 = ffma2(Wz2[1], h0.y, az1);
            an0 = ffma2(Wn2[0], h0.x, an0); an1 = ffma2(Wn2[1], h0.y, an1);
            ar0 = ffma2(Wr2[2], h1.x, ar0); ar1 = ffma2(Wr2[3], h1.y, ar1);
            az0 = ffma2(Wz2[2], h1.x, az0); az1 = ffma2(Wz2[3], h1.y, az1);
            an0 = ffma2(Wn2[2], h1.x, an0); an1 = ffma2(Wn2[3], h1.y, an1);
            ar0 = ffma2(Wr2[4], h2.x, ar0); ar1 = ffma2(Wr2[5], h2.y, ar1);
            az0 = ffma2(Wz2[4], h2.x, az0); az1 = ffma2(Wz2[5], h2.y, az1);
            an0 = ffma2(Wn2[4], h2.x, an0); an1 = ffma2(Wn2[5], h2.y, an1);
            ar0 = ffma2(Wr2[6], h3.x, ar0); ar1 = ffma2(Wr2[7], h3.y, ar1);
            az0 = ffma2(Wz2[6], h3.x, az0); az1 = ffma2(Wz2[7], h3.y, az1);
            an0 = ffma2(Wn2[6], h3.x, an0); an1 = ffma2(Wn2[7], h3.y, an1);
        }

        // ---- PHASE B: single poll for the 3 remote blocks ----
        while (__any_sync(0xFFFFFFFFu,
                (ldvol32(pB1 + qb) == CANARY) | (ldvol32(pB1 + qb + 128) == CANARY) |
                (ldvol32(pB2 + qb) == CANARY) | (ldvol32(pB2 + qb + 128) == CANARY) |
                (ldvol32(pB3 + qb) == CANARY) | (ldvol32(pB3 + qb + 128) == CANARY))) { }

        // re-canary buf (q+2)&3 (all cluster warps provably >= s-1 here)
        asm volatile("st.shared.u32 [%0], %1;"
                     :: "r"(ca + (uint32_t)((q + 2) & 3) * 1088), "r"(CANARY)
                     : "memory");

        // remote dots (3 blocks x 24 ffma2)
        {
            const int dbs[3] = {dbB1, dbB2, dbB3};
#pragma unroll
            for (int i = 1; i < 4; ++i) {
                const float* hp = hq + dbs[i - 1];
                ulonglong2 h0 = *(const ulonglong2*)(hp);
                ulonglong2 h1 = *(const ulonglong2*)(hp + 4);
                ulonglong2 h2 = *(const ulonglong2*)(hp + 8);
                ulonglong2 h3 = *(const ulonglong2*)(hp + 12);
                ar0 = ffma2(Wr2[i * 8 + 0], h0.x, ar0); ar1 = ffma2(Wr2[i * 8 + 1], h0.y, ar1);
                az0 = ffma2(Wz2[i * 8 + 0], h0.x, az0); az1 = ffma2(Wz2[i * 8 + 1], h0.y, az1);
                an0 = ffma2(Wn2[i * 8 + 0], h0.x, an0); an1 = ffma2(Wn2[i * 8 + 1], h0.y, an1);
                ar0 = ffma2(Wr2[i * 8 + 2], h1.x, ar0); ar1 = ffma2(Wr2[i * 8 + 3], h1.y, ar1);
                az0 = ffma2(Wz2[i * 8 + 2], h1.x, az0); az1 = ffma2(Wz2[i * 8 + 3], h1.y, az1);
                an0 = ffma2(Wn2[i * 8 + 2], h1.x, an0); an1 = ffma2(Wn2[i * 8 + 3], h1.y, an1);
                ar0 = ffma2(Wr2[i * 8 + 4], h2.x, ar0); ar1 = ffma2(Wr2[i * 8 + 5], h2.y, ar1);
                az0 = ffma2(Wz2[i * 8 + 4], h2.x, az0); az1 = ffma2(Wz2[i * 8 + 5], h2.y, az1);
                an0 = ffma2(Wn2[i * 8 + 4], h2.x, an0); an1 = ffma2(Wn2[i * 8 + 5], h2.y, an1);
                ar0 = ffma2(Wr2[i * 8 + 6], h3.x, ar0); ar1 = ffma2(Wr2[i * 8 + 7], h3.y, ar1);
                az0 = ffma2(Wz2[i * 8 + 6], h3.x, az0); az1 = ffma2(Wz2[i * 8 + 7], h3.y, az1);
                an0 = ffma2(Wn2[i * 8 + 6], h3.x, an0); an1 = ffma2(Wn2[i * 8 + 7], h3.y, an1);
            }
        }

        float sr = sum2(fadd2(ar0, ar1));
        float sz = sum2(fadd2(az0, az1));
        float sn = sum2(fadd2(an0, an1));
        // reduce over ss (lanes differing in bits 3,4)
        sr += __shfl_xor_sync(0xFFFFFFFFu, sr, 8);
        sz += __shfl_xor_sync(0xFFFFFFFFu, sz, 8);
        sn += __shfl_xor_sync(0xFFFFFFFFu, sn, 8);
        sr += __shfl_xor_sync(0xFFFFFFFFu, sr, 16);
        sz += __shfl_xor_sync(0xFFFFFFFFu, sz, 16);
        sn += __shfl_xor_sync(0xFFFFFFFFu, sn, 16);

        float gr = __shfl_sync(0xFFFFFFFFu, gv0, j);
        float gz = __shfl_sync(0xFFFFFFFFu, gv0, 8 + j);
        float gn = __shfl_sync(0xFFFFFFFFu, gv0, 16 + j);

        {
            float r = fast_sigmoid(gr + sr);
            float z = fast_sigmoid(gz + sz);
            float n = fast_tanh(fmaf(r, sn + bhn_u, gn));
            hprev = fmaf(z, hprev - n, n);
        }

        // send (R10 coalesced form, unchanged)
        if (s + 1 < T_) {
            const uint32_t qoff = (uint32_t)((s + 1) & 3) * 1088;
            const int base = (lane & 1) * 4;
            float4 v;
            v.x = __shfl_sync(0xFFFFFFFFu, hprev, base + 0);
            v.y = __shfl_sync(0xFFFFFFFFu, hprev, base + 1);
            v.z = __shfl_sync(0xFFFFFFFFu, hprev, base + 2);
            v.w = __shfl_sync(0xFFFFFFFFu, hprev, base + 3);
            if (lane < 8) {
                asm volatile("st.shared::cluster.v4.b32 [%0], {%1, %2, %3, %4};"
                             :: "r"(sdata + qoff),
                                "r"(__float_as_uint(v.x)), "r"(__float_as_uint(v.y)),
                                "r"(__float_as_uint(v.z)), "r"(__float_as_uint(v.w))
                             : "memory");
            }
            gv0 = gv1; gv1 = gv2;
            if (lane < 24 && s + 3 < T_) {
                const int tn = d ? (T_ - 4 - s) : (s + 3);
                gv2 = __ldg(xgp + (size_t)tn * G_ + lane);
            }
        }

        if (lane < 8) hist[s & 15][w * 8 + lane] = hprev;

        if ((s & 7) == 7) {
            const int rr = s - 14 + w;
            if (rr >= 0) {
                const int tw = d ? (T_ - 1 - rr) : rr;
                *(float2*)&g_outc[((size_t)b * T_ + tw) * 512 + d * 256 +
                                  rank * 64 + lane * 2] =
                    *(const float2*)&hist[rr & 15][lane * 2];
            }
            if ((s & 127) == 127 && lane == 0) {
                __threadfence();
                asm volatile("red.release.gpu.global.add.u32 [%0], %1;"
                             :: "l"(prog), "r"(1u) : "memory");
            }
        }
    }

    __syncthreads();
    if (w >= 1) {
        const int rr = 4088 + w;
        const int tw = d ? (T_ - 1 - rr) : rr;
        *(float2*)&g_outc[((size_t)b * T_ + tw) * 512 + d * 256 +
                          rank * 64 + lane * 2] =
            *(const float2*)&hist[rr & 15][lane * 2];
    }
    if (lane == 0) {
        __threadfence();
        asm volatile("red.release.gpu.global.add.u32 [%0], %1;"
                     :: "l"(prog), "r"(1u) : "memory");
    }

    asm volatile("barrier.cluster.arrive.aligned;" ::: "memory");
    asm volatile("barrier.cluster.wait.aligned;"   ::: "memory");

    heads_loop(Wm, bm, Wv, bv, out, As, Bs, &s_idx);
}

// ---------------------------------------------------------------------------
extern "C" void kernel_launch(void* const* d_in, const int* in_sizes, int n_in,
                              void* d_out, int out_size)
{
    const float* inputs = (const float*)d_in[0];
    const float* Wi_f   = (const float*)d_in[1];
    const float* bi_f   = (const float*)d_in[2];
    const float* Wh_f   = (const float*)d_in[3];
    const float* bhn_f  = (const float*)d_in[4];
    const float* Wi_b   = (const float*)d_in[5];
    const float* bi_b   = (const float*)d_in[6];
    const float* Wh_b   = (const float*)d_in[7];
    const float* bhn_b  = (const float*)d_in[8];
    const float* Wm     = (const float*)d_in[9];
    const float* bm     = (const float*)d_in[10];
    const float* Wv     = (const float*)d_in[11];
    const float* bv     = (const float*)d_in[12];
    float* out = (float*)d_out;

    (void)in_sizes; (void)n_in; (void)out_size;

    k_init<<<1, 512>>>();
    k_mega<<<148, 256>>>(inputs, Wi_f, bi_f, Wi_b, bi_b,
                         Wh_f, bhn_f, Wh_b, bhn_b,
                         Wm, bm, Wv, bv, out);
}

// round 17
// speedup vs baseline: 1.0704x; 1.0704x over previous
#include <cuda_runtime.h>
#include <cstdint>

#define B_ 8
#define T_ 4096
#define D_ 256
#define H_ 256
#define G_ 768              // 3H
#define M_ (B_ * T_)        // 32768
#define CANARY 0x7FC00001u  // NaN pattern; h is always finite
#define NTILES 6144         // xgemm: 2 dirs x 256 m-tiles x 12 n-tiles
#define NHTILES 2048        // heads: 256 m-tiles x 8 n-blocks

// Scratch (static device allocations only)
// xg layout (scan-permuted): [d][b][t][rank(4)][w(8)][gate(3)][j(8)]
__device__ float g_xg[(size_t)2 * B_ * T_ * G_];
__device__ float g_outc[(size_t)B_ * T_ * 2 * H_];     // [b][t][512]  (fwd | bwd)
__device__ unsigned g_cnt[2 * 8 * 32];                 // [d][b][tc] xg tile counters
__device__ unsigned g_prog[2 * 8];                     // [d][b] scan progress (32/epoch)
__device__ unsigned g_tilectr;                         // xgemm work queue
__device__ unsigned g_headctr;                         // heads work queue

typedef unsigned long long ull;

__device__ __forceinline__ uint32_t s2u(const void* p) {
    uint32_t a;
    asm("{ .reg .u64 t; cvta.to.shared.u64 t, %1; cvt.u32.u64 %0, t; }"
        : "=r"(a) : "l"(p));
    return a;
}
__device__ __forceinline__ ull ffma2(ull a, ull b, ull c) {
    ull d;
    asm("fma.rn.f32x2 %0, %1, %2, %3;" : "=l"(d) : "l"(a), "l"(b), "l"(c));
    return d;
}
__device__ __forceinline__ ull fadd2(ull a, ull b) {
    ull d;
    asm("add.rn.f32x2 %0, %1, %2;" : "=l"(d) : "l"(a), "l"(b));
    return d;
}
__device__ __forceinline__ ull pack2(float lo, float hi) {
    ull r;
    asm("mov.b64 %0, {%1, %2};" : "=l"(r)
        : "r"(__float_as_uint(lo)), "r"(__float_as_uint(hi)));
    return r;
}
__device__ __forceinline__ ull dup2(float v) {
    ull r;
    asm("mov.b64 %0, {%1, %1};" : "=l"(r) : "r"(__float_as_uint(v)));
    return r;
}
__device__ __forceinline__ void unpack2(ull a, float& lo, float& hi) {
    uint32_t l, h;
    asm("mov.b64 {%0, %1}, %2;" : "=r"(l), "=r"(h) : "l"(a));
    lo = __uint_as_float(l); hi = __uint_as_float(h);
}
__device__ __forceinline__ float sum2(ull a) {
    float lo, hi; unpack2(a, lo, hi); return lo + hi;
}
__device__ __forceinline__ float fast_sigmoid(float x) {
    float e, r;
    asm("ex2.approx.f32 %0, %1;" : "=f"(e) : "f"(-1.4426950408889634f * x));
    asm("rcp.approx.f32 %0, %1;" : "=f"(r) : "f"(1.0f + e));
    return r;
}
__device__ __forceinline__ float fast_tanh(float x) {
    float e, r;
    asm("ex2.approx.f32 %0, %1;" : "=f"(e) : "f"(-2.8853900817779268f * x));
    asm("rcp.approx.f32 %0, %1;" : "=f"(r) : "f"(1.0f + e));
    return fmaf(2.0f, r, -1.0f);
}
__device__ __forceinline__ float fast_exp(float x) {
    float e;
    asm("ex2.approx.f32 %0, %1;" : "=f"(e) : "f"(1.4426950408889634f * x));
    return e;
}
__device__ __forceinline__ unsigned ldacq_g(const unsigned* p) {
    unsigned v;
    asm volatile("ld.acquire.gpu.global.u32 %0, [%1];" : "=r"(v) : "l"(p));
    return v;
}
__device__ __forceinline__ void wait_cnt12(const unsigned* p) {
    while (ldacq_g(p) < 12u) { }
}

// ---------------------------------------------------------------------------
// k_init: reset all counters (stream-ordered before k_mega).
// ---------------------------------------------------------------------------
__global__ void k_init() {
    int t = threadIdx.x;
    if (t < 512) g_cnt[t] = 0u;
    if (t < 16)  g_prog[t] = 0u;
    if (t == 0)  { g_tilectr = 0u; g_headctr = 0u; }
}

// ---------------------------------------------------------------------------
// One 128x64 xgemm tile (FFMA2, double-buffered), permuted store to g_xg.
// ---------------------------------------------------------------------------
__device__ __forceinline__ void gemm_tile(
    const float* __restrict__ X, const float* __restrict__ W,
    const float* __restrict__ bi, float* __restrict__ out,
    int m0, int n0,
    float (&As)[2][16][136], float (&Bs)[2][16][68])
{
    const int tid = threadIdx.x;
    const int ti = tid >> 4;
    const int tj = tid & 15;
    const int ar = tid >> 4, ac = tid & 15;
    const int br = tid >> 6, bc = tid & 63;

    ull acc2[4][4];
#pragma unroll
    for (int i = 0; i < 4; ++i)
#pragma unroll
        for (int j = 0; j < 4; ++j) acc2[i][j] = 0ull;

#pragma unroll
    for (int p = 0; p < 8; ++p)
        As[0][ac][ar + p * 16] = X[(size_t)(m0 + ar + p * 16) * D_ + ac];
#pragma unroll
    for (int p = 0; p < 4; ++p)
        Bs[0][br + p * 4][bc] = W[(size_t)(br + p * 4) * G_ + n0 + bc];
    __syncthreads();

    int buf = 0;
    for (int k0 = 0; k0 < D_; k0 += 16) {
        float xa[8], xb[4];
        if (k0 + 16 < D_) {
#pragma unroll
            for (int p = 0; p < 8; ++p)
                xa[p] = X[(size_t)(m0 + ar + p * 16) * D_ + k0 + 16 + ac];
#pragma unroll
            for (int p = 0; p < 4; ++p)
                xb[p] = W[(size_t)(k0 + 16 + br + p * 4) * G_ + n0 + bc];
        }
#pragma unroll
        for (int kk = 0; kk < 16; ++kk) {
            ull ap[4];
            const ull* arow = (const ull*)&As[buf][kk][ti * 8];
            ap[0] = arow[0]; ap[1] = arow[1]; ap[2] = arow[2]; ap[3] = arow[3];
            float4 bq = *(const float4*)&Bs[buf][kk][tj * 4];
            ull bd[4];
            bd[0] = dup2(bq.x); bd[1] = dup2(bq.y);
            bd[2] = dup2(bq.z); bd[3] = dup2(bq.w);
#pragma unroll
            for (int i = 0; i < 4; ++i)
#pragma unroll
                for (int j = 0; j < 4; ++j)
                    acc2[i][j] = ffma2(ap[i], bd[j], acc2[i][j]);
        }
        if (k0 + 16 < D_) {
#pragma unroll
            for (int p = 0; p < 8; ++p) As[buf ^ 1][ac][ar + p * 16] = xa[p];
#pragma unroll
            for (int p = 0; p < 4; ++p) Bs[buf ^ 1][br + p * 4][bc] = xb[p];
            __syncthreads();
            buf ^= 1;
        }
    }

    const int n = n0 + tj * 4;
    const int g = n >> 8, u = n & 255;
    const int pos = (u >> 6) * 192 + ((u >> 3) & 7) * 24 + g * 8 + (u & 7);
    float4 bb = *(const float4*)&bi[n];
#pragma unroll
    for (int i = 0; i < 4; ++i) {
        float4 o0, o1;
        unpack2(acc2[i][0], o0.x, o1.x);
        unpack2(acc2[i][1], o0.y, o1.y);
        unpack2(acc2[i][2], o0.z, o1.z);
        unpack2(acc2[i][3], o0.w, o1.w);
        o0.x += bb.x; o0.y += bb.y; o0.z += bb.z; o0.w += bb.w;
        o1.x += bb.x; o1.y += bb.y; o1.z += bb.z; o1.w += bb.w;
        *(float4*)&out[(size_t)(m0 + ti * 8 + i * 2)     * G_ + pos] = o0;
        *(float4*)&out[(size_t)(m0 + ti * 8 + i * 2 + 1) * G_ + pos] = o1;
    }
}

// ---------------------------------------------------------------------------
// One 128x64 heads tile (FFMA2, double-buffered, fast-exp epilogue).
// ---------------------------------------------------------------------------
__device__ __forceinline__ void heads_tile(
    const float* __restrict__ W, const float* __restrict__ bbp, bool isV,
    int m0, int nw, float* __restrict__ out,
    float (&As)[2][16][136], float (&Bs)[2][16][68])
{
    const int tid = threadIdx.x;
    const int ti = tid >> 4, tj = tid & 15;
    const int ar = tid >> 4, ac = tid & 15;
    const int br = tid >> 6, bc = tid & 63;

    ull acc2[4][4];
#pragma unroll
    for (int i = 0; i < 4; ++i)
#pragma unroll
        for (int j = 0; j < 4; ++j) acc2[i][j] = 0ull;

#pragma unroll
    for (int p = 0; p < 8; ++p)
        As[0][ac][ar + p * 16] = g_outc[(size_t)(m0 + ar + p * 16) * 512 + ac];
#pragma unroll
    for (int p = 0; p < 4; ++p)
        Bs[0][br + p * 4][bc] = W[(size_t)(br + p * 4) * 256 + nw + bc];
    __syncthreads();

    int buf = 0;
    for (int k0 = 0; k0 < 512; k0 += 16) {
        float xa[8], xb[4];
        if (k0 + 16 < 512) {
#pragma unroll
            for (int p = 0; p < 8; ++p)
                xa[p] = g_outc[(size_t)(m0 + ar + p * 16) * 512 + k0 + 16 + ac];
#pragma unroll
            for (int p = 0; p < 4; ++p)
                xb[p] = W[(size_t)(k0 + 16 + br + p * 4) * 256 + nw + bc];
        }
#pragma unroll
        for (int kk = 0; kk < 16; ++kk) {
            ull ap[4];
            const ull* arow = (const ull*)&As[buf][kk][ti * 8];
            ap[0] = arow[0]; ap[1] = arow[1]; ap[2] = arow[2]; ap[3] = arow[3];
            float4 bq = *(const float4*)&Bs[buf][kk][tj * 4];
            ull bd[4];
            bd[0] = dup2(bq.x); bd[1] = dup2(bq.y);
            bd[2] = dup2(bq.z); bd[3] = dup2(bq.w);
#pragma unroll
            for (int i = 0; i < 4; ++i)
#pragma unroll
                for (int jj = 0; jj < 4; ++jj)
                    acc2[i][jj] = ffma2(ap[i], bd[jj], acc2[i][jj]);
        }
        if (k0 + 16 < 512) {
#pragma unroll
            for (int p = 0; p < 8; ++p) As[buf ^ 1][ac][ar + p * 16] = xa[p];
#pragma unroll
            for (int p = 0; p < 4; ++p) Bs[buf ^ 1][br + p * 4][bc] = xb[p];
            __syncthreads();
            buf ^= 1;
        }
    }

    const size_t hofs = (size_t)M_ * H_;
    float4 bb4 = *(const float4*)&bbp[nw + tj * 4];
#pragma unroll
    for (int i = 0; i < 4; ++i) {
        float4 o0, o1;
        unpack2(acc2[i][0], o0.x, o1.x);
        unpack2(acc2[i][1], o0.y, o1.y);
        unpack2(acc2[i][2], o0.z, o1.z);
        unpack2(acc2[i][3], o0.w, o1.w);
        o0.x += bb4.x; o0.y += bb4.y; o0.z += bb4.z; o0.w += bb4.w;
        o1.x += bb4.x; o1.y += bb4.y; o1.z += bb4.z; o1.w += bb4.w;
        int r0 = m0 + ti * 8 + i * 2, r1 = r0 + 1;
        if (isV) {
            o0.x = fast_exp(o0.x); o0.y = fast_exp(o0.y);
            o0.z = fast_exp(o0.z); o0.w = fast_exp(o0.w);
            o1.x = fast_exp(o1.x); o1.y = fast_exp(o1.y);
            o1.z = fast_exp(o1.z); o1.w = fast_exp(o1.w);
            *(float4*)&out[(size_t)r0 * 256 + nw + tj * 4] = o0;
            *(float4*)&out[(size_t)r1 * 256 + nw + tj * 4] = o1;
        } else {
            *(float4*)&out[hofs + (size_t)r0 * 256 + nw + tj * 4] = o0;
            *(float4*)&out[hofs + (size_t)r1 * 256 + nw + tj * 4] = o1;
        }
    }
}

// ---------------------------------------------------------------------------
// heads_loop: pull heads tiles (unlock-epoch priority), wait on scan progress.
// ---------------------------------------------------------------------------
__device__ void heads_loop(
    const float* Wm, const float* bm, const float* Wv, const float* bv,
    float* out, float (&As)[2][16][136], float (&Bs)[2][16][68], int* s_idx)
{
    const int tid = threadIdx.x;
    for (;;) {
        if (tid == 0) *s_idx = (int)atomicAdd(&g_headctr, 1u);
        __syncthreads();
        const int hidx = *s_idx;
        if (hidx >= NHTILES) break;

        const int k   = hidx >> 7;
        const int sub = hidx & 127;
        const int tc  = (sub & 1) ? (16 + k) : (15 - k);
        const int b   = (sub >> 1) & 7;
        const int nb  = sub >> 4;
        const int m0  = (b * 32 + tc) * 128;
        const int n0  = nb * 64;
        const bool isV = (n0 >= 256);
        const int nw  = n0 & 255;

        const unsigned ef = (unsigned)(tc + 2);
        const unsigned eb = (unsigned)((tc == 0) ? 33 : (33 - tc));
        if (tid == 0) {
            const unsigned* pf = &g_prog[b];
            const unsigned* pb = &g_prog[8 + b];
            while (ldacq_g(pf) < 32u * ef) __nanosleep(256);
            while (ldacq_g(pb) < 32u * eb) __nanosleep(256);
        }
        __syncthreads();

        heads_tile(isV ? Wv : Wm, isV ? bv : bm, isV, m0, nw, out, As, Bs);
    }
}

// ---------------------------------------------------------------------------
// k_mega: 37 clusters x 4 CTAs.
//   blockIdx 0..63  : GRU scan (frozen R10/R15 protocol) + progress publish,
//                     then joins the heads queue (no cluster barrier needed:
//                     step T-1's canary poll proves all peer writes landed,
//                     and the CTA stays resident through heads_loop).
//   blockIdx 64..147: xgemm workers -> heads workers.
// ---------------------------------------------------------------------------
__global__ void __launch_bounds__(256, 1) __cluster_dims__(4, 1, 1)
k_mega(const float* __restrict__ X,
       const float* __restrict__ Wi_f, const float* __restrict__ bi_f,
       const float* __restrict__ Wi_b, const float* __restrict__ bi_b,
       const float* __restrict__ Wh_f, const float* __restrict__ bhn_f,
       const float* __restrict__ Wh_b, const float* __restrict__ bhn_b,
       const float* __restrict__ Wm, const float* __restrict__ bm,
       const float* __restrict__ Wv, const float* __restrict__ bv,
       float* __restrict__ out)
{
    __shared__ __align__(16) float As[2][16][136];   // gemm/heads tiles
    __shared__ __align__(16) float Bs[2][16][68];
    __shared__ __align__(16) float hbuf[4][272];     // scan ring
    __shared__ __align__(16) float hist[16][64];     // scan output staging
    __shared__ int s_idx;

    const int tid = threadIdx.x;

    if (blockIdx.x >= 64) {
        // ================= WORKER PATH =================
        for (;;) {
            if (tid == 0) s_idx = (int)atomicAdd(&g_tilectr, 1u);
            __syncthreads();
            const int idx = s_idx;
            if (idx >= NTILES) break;

            const int k  = idx / 96;
            const int r  = idx - k * 96;
            const int bb = r / 12;
            const int bx = r - bb * 12;
            const int dd = k & 1;
            const int ii = k >> 1;
            const int tc = dd ? (31 - ii) : ii;
            const int m0 = (bb * 32 + tc) * 128;
            const int n0 = bx * 64;

            gemm_tile(X, dd ? Wi_b : Wi_f, dd ? bi_b : bi_f,
                      g_xg + (size_t)dd * M_ * G_, m0, n0, As, Bs);

            __threadfence();
            __syncthreads();
            if (tid == 0) {
                const unsigned* p = &g_cnt[(dd * 8 + bb) * 32 + tc];
                asm volatile("red.release.gpu.global.add.u32 [%0], %1;"
                             :: "l"(p), "r"(1u) : "memory");
            }
        }
        heads_loop(Wm, bm, Wv, bv, out, As, Bs, &s_idx);
        return;
    }

    // ================= SCAN PATH (frozen protocol) =================
    const uint32_t hbuf_a = s2u(hbuf);

    const int rank = blockIdx.x & 3;
    const int cid  = blockIdx.x >> 2;
    const int d    = cid >> 3;
    const int b    = cid & 7;

    const float* Wh  = d ? Wh_b  : Wh_f;
    const float* bhn = d ? bhn_b : bhn_f;

    const int w    = tid >> 5;
    const int lane = tid & 31;
    const int kq   = lane >> 3;
    const int j    = lane & 7;
    const int unit = rank * 64 + w * 8 + j;
    const unsigned* cbase = &g_cnt[(d * 8 + b) * 32];
    unsigned* prog = &g_prog[d * 8 + b];

    ull Wr2[32], Wz2[32], Wn2[32];
#pragma unroll
    for (int kk = 0; kk < 32; ++kk) {
        size_t r0 = (size_t)(kq * 64 + kk * 2) * G_;
        size_t r1 = r0 + G_;
        Wr2[kk] = pack2(__ldg(Wh + r0 + unit),       __ldg(Wh + r1 + unit));
        Wz2[kk] = pack2(__ldg(Wh + r0 + 256 + unit), __ldg(Wh + r1 + 256 + unit));
        Wn2[kk] = pack2(__ldg(Wh + r0 + 512 + unit), __ldg(Wh + r1 + 512 + unit));
    }

    for (int i = tid; i < 272; i += 256) {
        hbuf[0][i] = 0.f;
        ((unsigned*)hbuf[1])[i] = CANARY;
        ((unsigned*)hbuf[2])[i] = CANARY;
        ((unsigned*)hbuf[3])[i] = CANARY;
    }
    __syncthreads();
    asm volatile("barrier.cluster.arrive.aligned;" ::: "memory");
    asm volatile("barrier.cluster.wait.aligned;"   ::: "memory");

    uint32_t sdata = 0;
    if (lane < 8) {
        uint32_t peer = (uint32_t)((rank + (lane >> 1)) & 3);
        uint32_t rhb;
        asm("mapa.shared::cluster.u32 %0, %1, %2;" : "=r"(rhb) : "r"(hbuf_a), "r"(peer));
        sdata = rhb + (uint32_t)(rank * 272 + w * 32 + (lane & 1) * 16);
    }
    const uint32_t pa = hbuf_a + (uint32_t)(kq * 272 + j * 32);
    const uint32_t ca = hbuf_a + (uint32_t)((w >> 1) * 272 + (w & 1) * 128 + lane * 4);

    const float bhn_u = bhn[unit];
    const float* xgp = g_xg + ((size_t)(d * B_ + b)) * T_ * G_ + rank * 192 + w * 24;

    wait_cnt12(cbase + (d ? 31 : 0));
    wait_cnt12(cbase + (d ? 30 : 1));

    float gv0 = 0.f, gv1 = 0.f, gv2 = 0.f;
    if (lane < 24) {
        gv0 = __ldg(xgp + (size_t)(d ? T_ - 1 : 0) * G_ + lane);
        gv1 = __ldg(xgp + (size_t)(d ? T_ - 2 : 1) * G_ + lane);
        gv2 = __ldg(xgp + (size_t)(d ? T_ - 3 : 2) * G_ + lane);
    }

    float hprev = 0.f;

    for (int s = 0; s < T_; ++s) {
        const int q = s & 3;

        if ((s & 127) == 0 && s) {
            const int a = s >> 7;
            const int c0 = d ? (31 - a) : a;
            const int c1n = (a < 31) ? (a + 1) : 31;
            const int c1 = d ? (31 - c1n) : c1n;
            wait_cnt12(cbase + c0);
            wait_cnt12(cbase + c1);
        }

        // 1. poll canary
        {
            const uint32_t a = pa + (uint32_t)q * 1088;
            for (;;) {
                uint32_t x0, x1, x2, x3, y0, y1, y2, y3;
                asm volatile("ld.volatile.shared.v4.u32 {%0,%1,%2,%3}, [%4];"
                             : "=r"(x0), "=r"(x1), "=r"(x2), "=r"(x3) : "r"(a));
                asm volatile("ld.volatile.shared.v4.u32 {%0,%1,%2,%3}, [%4];"
                             : "=r"(y0), "=r"(y1), "=r"(y2), "=r"(y3) : "r"(a + 16));
                bool bad = (x0 == CANARY) | (x1 == CANARY) | (x2 == CANARY) |
                           (x3 == CANARY) | (y0 == CANARY) | (y1 == CANARY) |
                           (y2 == CANARY) | (y3 == CANARY);
                if (!__any_sync(0xFFFFFFFFu, bad)) break;
            }
        }

        // 2. re-canary buf (q+2)&3
        {
            const uint32_t a = ca + (uint32_t)((q + 2) & 3) * 1088;
            asm volatile("st.shared.u32 [%0], %1;" :: "r"(a), "r"(CANARY) : "memory");
        }

        // 3. dots
        const float* hp = &hbuf[q][kq * 68];
        ull ar0 = 0, ar1 = 0, az0 = 0, az1 = 0, an0 = 0, an1 = 0;
#pragma unroll
        for (int qq = 0; qq < 16; ++qq) {
            ulonglong2 hv2 = *(const ulonglong2*)(hp + qq * 4);
            ar0 = ffma2(Wr2[qq * 2],     hv2.x, ar0);
            ar1 = ffma2(Wr2[qq * 2 + 1], hv2.y, ar1);
            az0 = ffma2(Wz2[qq * 2],     hv2.x, az0);
            az1 = ffma2(Wz2[qq * 2 + 1], hv2.y, az1);
            an0 = ffma2(Wn2[qq * 2],     hv2.x, an0);
            an1 = ffma2(Wn2[qq * 2 + 1], hv2.y, an1);
        }
        float sr = sum2(fadd2(ar0, ar1));
        float sz = sum2(fadd2(az0, az1));
        float sn = sum2(fadd2(an0, an1));
#pragma unroll
        for (int m = 8; m <= 16; m <<= 1) {
            sr += __shfl_xor_sync(0xFFFFFFFFu, sr, m);
            sz += __shfl_xor_sync(0xFFFFFFFFu, sz, m);
            sn += __shfl_xor_sync(0xFFFFFFFFu, sn, m);
        }

        float gr = __shfl_sync(0xFFFFFFFFu, gv0, j);
        float gz = __shfl_sync(0xFFFFFFFFu, gv0, 8 + j);
        float gn = __shfl_sync(0xFFFFFFFFu, gv0, 16 + j);

        {
            float r = fast_sigmoid(gr + sr);
            float z = fast_sigmoid(gz + sz);
            float n = fast_tanh(fmaf(r, sn + bhn_u, gn));
            hprev = fmaf(z, hprev - n, n);
        }

        // 4. send
        if (s + 1 < T_) {
            const uint32_t qoff = (uint32_t)((s + 1) & 3) * 1088;
            const int base = (lane & 1) * 4;
            float4 v;
            v.x = __shfl_sync(0xFFFFFFFFu, hprev, base + 0);
            v.y = __shfl_sync(0xFFFFFFFFu, hprev, base + 1);
            v.z = __shfl_sync(0xFFFFFFFFu, hprev, base + 2);
            v.w = __shfl_sync(0xFFFFFFFFu, hprev, base + 3);
            if (lane < 8) {
                asm volatile("st.shared::cluster.v4.b32 [%0], {%1, %2, %3, %4};"
                             :: "r"(sdata + qoff),
                                "r"(__float_as_uint(v.x)), "r"(__float_as_uint(v.y)),
                                "r"(__float_as_uint(v.z)), "r"(__float_as_uint(v.w))
                             : "memory");
            }
            gv0 = gv1; gv1 = gv2;
            if (lane < 24 && s + 3 < T_) {
                const int tn = d ? (T_ - 4 - s) : (s + 3);
                gv2 = __ldg(xgp + (size_t)tn * G_ + lane);
            }
        }

        // 5. stage output
        if (lane < 8) hist[s & 15][w * 8 + lane] = hprev;

        // 6. skew-safe flush + progress publish
        if ((s & 7) == 7) {
            const int rr = s - 14 + w;
            if (rr >= 0) {
                const int tw = d ? (T_ - 1 - rr) : rr;
                *(float2*)&g_outc[((size_t)b * T_ + tw) * 512 + d * 256 +
                                  rank * 64 + lane * 2] =
                    *(const float2*)&hist[rr & 15][lane * 2];
            }
            if ((s & 127) == 127 && lane == 0) {
                __threadfence();
                asm volatile("red.release.gpu.global.add.u32 [%0], %1;"
                             :: "l"(prog), "r"(1u) : "memory");
            }
        }
    }

    // tail rows 4089..4095
    __syncthreads();
    if (w >= 1) {
        const int rr = 4088 + w;
        const int tw = d ? (T_ - 1 - rr) : rr;
        *(float2*)&g_outc[((size_t)b * T_ + tw) * 512 + d * 256 +
                          rank * 64 + lane * 2] =
            *(const float2*)&hist[rr & 15][lane * 2];
    }
    // epoch 33 publish
    if (lane == 0) {
        __threadfence();
        asm volatile("red.release.gpu.global.add.u32 [%0], %1;"
                     :: "l"(prog), "r"(1u) : "memory");
    }

    // No cluster barrier needed here: passing step T-1's canary poll proves
    // every peer's final remote store already landed, and this CTA stays
    // resident (smem intact) through heads_loop. Join the heads queue now.
    heads_loop(Wm, bm, Wv, bv, out, As, Bs, &s_idx);
}

// ---------------------------------------------------------------------------
extern "C" void kernel_launch(void* const* d_in, const int* in_sizes, int n_in,
                              void* d_out, int out_size)
{
    const float* inputs = (const float*)d_in[0];
    const float* Wi_f   = (const float*)d_in[1];
    const float* bi_f   = (const float*)d_in[2];
    const float* Wh_f   = (const float*)d_in[3];
    const float* bhn_f  = (const float*)d_in[4];
    const float* Wi_b   = (const float*)d_in[5];
    const float* bi_b   = (const float*)d_in[6];
    const float* Wh_b   = (const float*)d_in[7];
    const float* bhn_b  = (const float*)d_in[8];
    const float* Wm     = (const float*)d_in[9];
    const float* bm     = (const float*)d_in[10];
    const float* Wv     = (const float*)d_in[11];
    const float* bv     = (const float*)d_in[12];
    float* out = (float*)d_out;

    (void)in_sizes; (void)n_in; (void)out_size;

    k_init<<<1, 512>>>();
    k_mega<<<148, 256>>>(inputs, Wi_f, bi_f, Wi_b, bi_b,
                         Wh_f, bhn_f, Wh_b, bhn_b,
                         Wm, bm, Wv, bv, out);
}